// round 14
// baseline (speedup 1.0000x reference)
#include <cuda_runtime.h>
#include <cuda_bf16.h>
#include <math.h>
#include <stdint.h>

#define FULL 0xffffffffu

constexpr int B     = 4;
constexpr int NS    = 16384;
constexpr int NG    = 2048;
constexpr int D     = 128;
constexpr int NC1   = 5;
constexpr int NCELL = NC1*NC1*NC1; // 125
constexpr int TOT_S = B*NS;        // 65536
constexpr int TOT_G = B*NG;        // 8192
constexpr float INV_SIG2 = 0.16f;
constexpr float R2CUT = 64.0f;

// ---------------- scratch ----------------
__device__ int    d_s_cnt[B*NCELL];
__device__ int    d_g_cnt[B*NCELL];
__device__ int    d_s_start[B*NCELL+1];
__device__ int    d_g_start[B*NCELL+1];
__device__ int    d_s_cellid[TOT_S];
__device__ int    d_g_cellid[TOT_G];
__device__ int    d_s_items[TOT_S];
__device__ int    d_g_items[TOT_G];
__device__ float4 d_vs_s[TOT_S];
__device__ float4 d_vg_s[TOT_G];
__device__ float4 d_xs_hs[TOT_S*32];
__device__ float4 d_xg_hs[TOT_G*32];
__device__ float4 d_xs_ms[TOT_S*32];
__device__ float4 d_xg_ms[TOT_G*32];
__device__ float  d_invr[TOT_S];

__device__ __forceinline__ int clamp5(int c) { return c < 0 ? 0 : (c > 4 ? 4 : c); }
__device__ __forceinline__ int cell_of(float x, float y, float z) {
    int cx = clamp5((int)(x * 0.125f));
    int cy = clamp5((int)(y * 0.125f));
    int cz = clamp5((int)(z * 0.125f));
    return (cx * 5 + cy) * 5 + cz;
}

// ---------------- binning ----------------
__global__ void k_zero() {
    int t = blockIdx.x * blockDim.x + threadIdx.x;
    if (t < B*NCELL) { d_s_cnt[t] = 0; d_g_cnt[t] = 0; }
}

template<bool SURF>
__global__ void k_cellhist(const float* __restrict__ v) {
    constexpr int LOGN = SURF ? 14 : 11;
    int t = blockIdx.x * blockDim.x + threadIdx.x;
    int b = t >> LOGN;
    float x = v[3*t], y = v[3*t+1], z = v[3*t+2];
    int c = cell_of(x, y, z);
    (SURF ? d_s_cellid : d_g_cellid)[t] = c;
    atomicAdd((SURF ? d_s_cnt : d_g_cnt) + b*NCELL + c, 1);
}

__global__ void k_scan() {
    __shared__ int sh_s[512];
    __shared__ int sh_g[512];
    int t = threadIdx.x;
    sh_s[t] = (t < B*NCELL) ? d_s_cnt[t] : 0;
    sh_g[t] = (t < B*NCELL) ? d_g_cnt[t] : 0;
    __syncthreads();
    #pragma unroll
    for (int off = 1; off < 512; off <<= 1) {
        int as = sh_s[t], ag = sh_g[t];
        int us = (t >= off) ? sh_s[t - off] : 0;
        int ug = (t >= off) ? sh_g[t - off] : 0;
        __syncthreads();
        sh_s[t] = as + us;
        sh_g[t] = ag + ug;
        __syncthreads();
    }
    if (t <= B*NCELL) {
        d_s_start[t] = (t == 0) ? 0 : sh_s[t - 1];
        d_g_start[t] = (t == 0) ? 0 : sh_g[t - 1];
    }
}

template<bool SURF>
__global__ void k_build(const float* __restrict__ v) {
    constexpr int N = SURF ? NS : NG;
    int c = blockIdx.x;
    int b = threadIdx.x >> 5;
    int lane = threadIdx.x & 31;
    const int* startA = SURF ? d_s_start : d_g_start;
    const int* cellid = SURF ? d_s_cellid : d_g_cellid;
    int*       items  = SURF ? d_s_items : d_g_items;
    float4*    vsrt   = SURF ? d_vs_s   : d_vg_s;
    int pos = startA[b*NCELL + c];
    int bN  = b * N;
    const float* vb = v + (size_t)bN * 3;
    for (int base = 0; base < N; base += 32) {
        int n = base + lane;
        bool h = (cellid[bN + n] == c);
        unsigned m = __ballot_sync(FULL, h);
        if (h) {
            int p = pos + __popc(m & ((1u << lane) - 1u));
            items[p] = n;
            vsrt[p]  = make_float4(vb[3*n], vb[3*n+1], vb[3*n+2], 0.f);
        }
        pos += __popc(m);
    }
}

// =============== 3xBF16 tensor-core GEMM (m16n8k16) ===============
constexpr int GM   = 128;
constexpr int GT   = 256;
constexpr int BK   = 32;
constexpr int PSTR = 20;           // u32 stride per row (16 kp + 4 pad)

#define MMA_BF16(c, a, b0, b1)                                              \
    asm volatile("mma.sync.aligned.m16n8k16.row.col.f32.bf16.bf16.f32 "     \
        "{%0,%1,%2,%3}, {%4,%5,%6,%7}, {%8,%9}, {%0,%1,%2,%3};"             \
        : "+f"((c)[0]), "+f"((c)[1]), "+f"((c)[2]), "+f"((c)[3])            \
        : "r"((a)[0]), "r"((a)[1]), "r"((a)[2]), "r"((a)[3]),               \
          "r"(b0), "r"(b1))

__device__ __forceinline__ uint32_t pack_bf16x2(float e0, float e1) {
    uint32_t r;
    asm("cvt.rn.bf16x2.f32 %0, %1, %2;" : "=r"(r) : "f"(e1), "f"(e0));
    return r;
}
__device__ __forceinline__ float bf16_trunc(float x) {
    return __bfloat162float(__float2bfloat16_rn(x));
}

__device__ __forceinline__ void stage_a4(uint32_t* Ah, uint32_t* Al,
                                         float4 v, int row, int f4) {
    float h0 = bf16_trunc(v.x), h1 = bf16_trunc(v.y);
    float h2 = bf16_trunc(v.z), h3 = bf16_trunc(v.w);
    int idx = row * PSTR + f4 * 2;
    uint2 hp = make_uint2(pack_bf16x2(v.x, v.y), pack_bf16x2(v.z, v.w));
    uint2 lp = make_uint2(pack_bf16x2(v.x - h0, v.y - h1),
                          pack_bf16x2(v.z - h2, v.w - h3));
    *reinterpret_cast<uint2*>(Ah + idx) = hp;
    *reinterpret_cast<uint2*>(Al + idx) = lp;
}

__device__ __forceinline__ void stage_w_t(uint32_t* Wh, uint32_t* Wl,
                                          const float* __restrict__ W,
                                          int k0, int tid) {
    #pragma unroll
    for (int j = 0; j < 4; j++) {
        int item = tid + j * GT;
        int kk4 = item >> 7;
        int n   = item & 127;
        const float* wp = W + (size_t)(k0 + kk4 * 4) * D + n;
        float x0 = wp[0], x1 = wp[D], x2 = wp[2*D], x3 = wp[3*D];
        float h0 = bf16_trunc(x0), h1 = bf16_trunc(x1);
        float h2 = bf16_trunc(x2), h3 = bf16_trunc(x3);
        int idx = n * PSTR + kk4 * 2;
        *reinterpret_cast<uint2*>(Wh + idx) =
            make_uint2(pack_bf16x2(x0, x1), pack_bf16x2(x2, x3));
        *reinterpret_cast<uint2*>(Wl + idx) =
            make_uint2(pack_bf16x2(x0 - h0, x1 - h1), pack_bf16x2(x2 - h2, x3 - h3));
    }
}

__device__ __forceinline__ void mma_chunk(const uint32_t* Ah, const uint32_t* Al,
                                          const uint32_t* Wh, const uint32_t* Wl,
                                          float c[2][8][4],
                                          int warp_m, int warp_n, int qr, int qc) {
    #pragma unroll
    for (int kh = 0; kh < 2; kh++) {
        int kpb = kh * 8;
        uint32_t afh[2][4], afl[2][4];
        #pragma unroll
        for (int mt = 0; mt < 2; mt++) {
            int r0 = warp_m * 32 + mt * 16 + qr;
            int i0 = r0 * PSTR + kpb + qc;
            int i1 = (r0 + 8) * PSTR + kpb + qc;
            afh[mt][0] = Ah[i0];     afh[mt][1] = Ah[i1];
            afh[mt][2] = Ah[i0 + 4]; afh[mt][3] = Ah[i1 + 4];
            afl[mt][0] = Al[i0];     afl[mt][1] = Al[i1];
            afl[mt][2] = Al[i0 + 4]; afl[mt][3] = Al[i1 + 4];
        }
        #pragma unroll
        for (int nt = 0; nt < 8; nt++) {
            int cn = warp_n * 64 + nt * 8 + qr;
            int bi = cn * PSTR + kpb + qc;
            uint32_t bh0 = Wh[bi], bh1 = Wh[bi + 4];
            uint32_t bl0 = Wl[bi], bl1 = Wl[bi + 4];
            #pragma unroll
            for (int mt = 0; mt < 2; mt++) {
                MMA_BF16(c[mt][nt], afh[mt], bh0, bh1);
                MMA_BF16(c[mt][nt], afh[mt], bl0, bl1);
                MMA_BF16(c[mt][nt], afl[mt], bh0, bh1);
            }
        }
    }
}

template<bool SURF>
__global__ __launch_bounds__(GT)
void k_gemm_pre(const float* __restrict__ X, const float* __restrict__ W,
                const float* __restrict__ bias) {
    constexpr int LOGN = SURF ? 14 : 11;
    const int* items = SURF ? d_s_items : d_g_items;
    float*     OutF  = reinterpret_cast<float*>(SURF ? d_xs_hs : d_xg_hs);

    __shared__ uint32_t sAh[GM*PSTR], sAl[GM*PSTR], sWh[GM*PSTR], sWl[GM*PSTR];
    __shared__ int rowoff[GM];

    int tid = threadIdx.x;
    int i0  = blockIdx.x * GM;
    if (tid < GM) {
        int i = i0 + tid; int b = i >> LOGN; int n = items[i];
        rowoff[tid] = ((b << LOGN) + n) * D;
    }

    int wid = tid >> 5, lane = tid & 31;
    int warp_m = wid & 3, warp_n = wid >> 2;
    int qr = lane >> 2, qc = lane & 3;

    float c[2][8][4];
    #pragma unroll
    for (int mt = 0; mt < 2; mt++)
        #pragma unroll
        for (int nt = 0; nt < 8; nt++)
            #pragma unroll
            for (int e = 0; e < 4; e++) c[mt][nt][e] = 0.f;

    for (int k0 = 0; k0 < D; k0 += BK) {
        __syncthreads();
        stage_w_t(sWh, sWl, W, k0, tid);
        #pragma unroll
        for (int j = 0; j < 4; j++) {
            int item = tid + j * GT;
            int row = item >> 3;
            int f4  = item & 7;
            float4 v = *reinterpret_cast<const float4*>(X + rowoff[row] + k0 + f4 * 4);
            stage_a4(sAh, sAl, v, row, f4);
        }
        __syncthreads();
        mma_chunk(sAh, sAl, sWh, sWl, c, warp_m, warp_n, qr, qc);
    }

    #pragma unroll
    for (int mt = 0; mt < 2; mt++) {
        int gr0 = i0 + warp_m * 32 + mt * 16 + qr;
        #pragma unroll
        for (int nt = 0; nt < 8; nt++) {
            int cn = warp_n * 64 + nt * 8 + qc * 2;
            float b0v = bias[cn], b1v = bias[cn + 1];
            float2 o0, o1;
            o0.x = fmaxf(c[mt][nt][0] + b0v, 0.f);
            o0.y = fmaxf(c[mt][nt][1] + b1v, 0.f);
            o1.x = fmaxf(c[mt][nt][2] + b0v, 0.f);
            o1.y = fmaxf(c[mt][nt][3] + b1v, 0.f);
            *reinterpret_cast<float2*>(&OutF[(size_t)gr0 * D + cn]) = o0;
            *reinterpret_cast<float2*>(&OutF[(size_t)(gr0 + 8) * D + cn]) = o1;
        }
    }
}

template<bool SURF>
__global__ __launch_bounds__(GT)
void k_gemm_post(const float* __restrict__ W, const float* __restrict__ bias,
                 float* __restrict__ out) {
    constexpr int LOGN = SURF ? 14 : 11;
    constexpr int OB   = SURF ? 0 : NS;
    const float* Hf   = reinterpret_cast<const float*>(SURF ? d_xs_hs : d_xg_hs);
    const float* Mf   = reinterpret_cast<const float*>(SURF ? d_xs_ms : d_xg_ms);
    const int* items  = SURF ? d_s_items : d_g_items;

    __shared__ uint32_t sAh[GM*PSTR], sAl[GM*PSTR], sWh[GM*PSTR], sWl[GM*PSTR];
    __shared__ int orow[GM];

    int tid = threadIdx.x;
    int i0  = blockIdx.x * GM;
    if (tid < GM) {
        int i = i0 + tid; int b = i >> LOGN; int n = items[i];
        orow[tid] = b * (NS + NG) + OB + n;
    }

    int wid = tid >> 5, lane = tid & 31;
    int warp_m = wid & 3, warp_n = wid >> 2;
    int qr = lane >> 2, qc = lane & 3;

    float c[2][8][4];
    #pragma unroll
    for (int mt = 0; mt < 2; mt++)
        #pragma unroll
        for (int nt = 0; nt < 8; nt++)
            #pragma unroll
            for (int e = 0; e < 4; e++) c[mt][nt][e] = 0.f;

    for (int k0 = 0; k0 < 2 * D; k0 += BK) {
        __syncthreads();
        stage_w_t(sWh, sWl, W, k0, tid);
        const float* src = (k0 < D) ? Hf : Mf;
        int kl = k0 & (D - 1);
        #pragma unroll
        for (int j = 0; j < 4; j++) {
            int item = tid + j * GT;
            int row = item >> 3;
            int f4  = item & 7;
            float4 v = *reinterpret_cast<const float4*>(
                src + (size_t)(i0 + row) * D + kl + f4 * 4);
            stage_a4(sAh, sAl, v, row, f4);
        }
        __syncthreads();
        mma_chunk(sAh, sAl, sWh, sWl, c, warp_m, warp_n, qr, qc);
    }

    #pragma unroll
    for (int mt = 0; mt < 2; mt++) {
        int lr0 = warp_m * 32 + mt * 16 + qr;
        int gr0 = orow[lr0];
        int gr1 = orow[lr0 + 8];
        #pragma unroll
        for (int nt = 0; nt < 8; nt++) {
            int cn = warp_n * 64 + nt * 8 + qc * 2;
            float b0v = bias[cn], b1v = bias[cn + 1];
            float2 o0, o1;
            o0.x = fmaxf(c[mt][nt][0] + b0v, 0.f);
            o0.y = fmaxf(c[mt][nt][1] + b1v, 0.f);
            o1.x = fmaxf(c[mt][nt][2] + b0v, 0.f);
            o1.y = fmaxf(c[mt][nt][3] + b1v, 0.f);
            *reinterpret_cast<float2*>(&out[(size_t)gr0 * D + cn]) = o0;
            *reinterpret_cast<float2*>(&out[(size_t)gr1 * D + cn]) = o1;
        }
    }
}

// ---------------- message passing ----------------
// Hit loop now walks the (warp-uniform) ballot mask 4 hits at a time:
// extract 4 indices, issue 4 independent LDG.128s (MLP=4), then accumulate
// in the same ascending-ffs order as before (bit-identical arithmetic).
__global__ __launch_bounds__(512)
void k_mps() {
    int w    = blockIdx.x * 16 + (threadIdx.x >> 5);
    int lane = threadIdx.x & 31;
    int b    = w >> 14;
    float4 p = d_vs_s[w];
    int cx = clamp5((int)(p.x * 0.125f));
    int cy = clamp5((int)(p.y * 0.125f));
    int cz = clamp5((int)(p.z * 0.125f));
    int z0 = cz > 0 ? cz - 1 : 0;
    int z1 = cz < 4 ? cz + 1 : 4;

    float4 acc = make_float4(0.f, 0.f, 0.f, 0.f);
    float rs = 0.f;

    for (int dx = -1; dx <= 1; dx++) {
        int X = cx + dx; if ((unsigned)X > 4u) continue;
        for (int dy = -1; dy <= 1; dy++) {
            int Y = cy + dy; if ((unsigned)Y > 4u) continue;
            int cb = b * NCELL + (X * 5 + Y) * 5;
            int s0 = d_g_start[cb + z0], s1 = d_g_start[cb + z1 + 1];
            for (int base = s0; base < s1; base += 32) {
                int j = base + lane;
                float wv = 0.f;
                if (j < s1) {
                    float4 q = d_vg_s[j];
                    float ddx = p.x - q.x;
                    float ddy = p.y - q.y;
                    float ddz = p.z - q.z;
                    float d2 = ddx*ddx + ddy*ddy + ddz*ddz;
                    if (d2 < R2CUT) wv = __expf(-INV_SIG2 * d2);
                }
                rs += wv;
                unsigned m = __ballot_sync(FULL, wv > 0.f);
                while (m) {
                    int t0 = __ffs(m) - 1; m &= m - 1;
                    int t1 = __ffs(m) - 1; m &= m - 1;   // -1 if none; m stays 0
                    int t2 = __ffs(m) - 1; m &= m - 1;
                    int t3 = __ffs(m) - 1; m &= m - 1;
                    float w0 = __shfl_sync(FULL, wv, t0);
                    float w1 = __shfl_sync(FULL, wv, t1 & 31);
                    float w2 = __shfl_sync(FULL, wv, t2 & 31);
                    float w3 = __shfl_sync(FULL, wv, t3 & 31);
                    float4 g0 = d_xg_hs[(size_t)(base + t0) * 32 + lane];
                    float4 g1, g2, g3;
                    if (t1 >= 0) g1 = d_xg_hs[(size_t)(base + t1) * 32 + lane];
                    if (t2 >= 0) g2 = d_xg_hs[(size_t)(base + t2) * 32 + lane];
                    if (t3 >= 0) g3 = d_xg_hs[(size_t)(base + t3) * 32 + lane];
                    acc.x += w0*g0.x; acc.y += w0*g0.y; acc.z += w0*g0.z; acc.w += w0*g0.w;
                    if (t1 >= 0) { acc.x += w1*g1.x; acc.y += w1*g1.y; acc.z += w1*g1.z; acc.w += w1*g1.w; }
                    if (t2 >= 0) { acc.x += w2*g2.x; acc.y += w2*g2.y; acc.z += w2*g2.z; acc.w += w2*g2.w; }
                    if (t3 >= 0) { acc.x += w3*g3.x; acc.y += w3*g3.y; acc.z += w3*g3.z; acc.w += w3*g3.w; }
                }
            }
        }
    }
    #pragma unroll
    for (int o = 16; o; o >>= 1) rs += __shfl_xor_sync(FULL, rs, o);
    float inv = 1.f / (rs + 1e-8f);
    acc.x *= inv; acc.y *= inv; acc.z *= inv; acc.w *= inv;
    d_xs_ms[(size_t)w * 32 + lane] = acc;
    if (lane == 0) d_invr[w] = inv;
}

__global__ __launch_bounds__(512)
void k_mpg() {
    int w    = blockIdx.x * 16 + (threadIdx.x >> 5);
    int lane = threadIdx.x & 31;
    int b    = w >> 11;
    float4 p = d_vg_s[w];
    int cx = clamp5((int)(p.x * 0.125f));
    int cy = clamp5((int)(p.y * 0.125f));
    int cz = clamp5((int)(p.z * 0.125f));
    int z0 = cz > 0 ? cz - 1 : 0;
    int z1 = cz < 4 ? cz + 1 : 4;

    float4 acc = make_float4(0.f, 0.f, 0.f, 0.f);

    for (int dx = -1; dx <= 1; dx++) {
        int X = cx + dx; if ((unsigned)X > 4u) continue;
        for (int dy = -1; dy <= 1; dy++) {
            int Y = cy + dy; if ((unsigned)Y > 4u) continue;
            int cb = b * NCELL + (X * 5 + Y) * 5;
            int s0 = d_s_start[cb + z0], s1 = d_s_start[cb + z1 + 1];
            for (int base = s0; base < s1; base += 32) {
                int j = base + lane;
                float wv = 0.f;
                if (j < s1) {
                    float4 q = d_vs_s[j];
                    float ddx = p.x - q.x;
                    float ddy = p.y - q.y;
                    float ddz = p.z - q.z;
                    float d2 = ddx*ddx + ddy*ddy + ddz*ddz;
                    if (d2 < R2CUT) wv = __expf(-INV_SIG2 * d2) * d_invr[j];
                }
                unsigned m = __ballot_sync(FULL, wv > 0.f);
                while (m) {
                    int t0 = __ffs(m) - 1; m &= m - 1;
                    int t1 = __ffs(m) - 1; m &= m - 1;
                    int t2 = __ffs(m) - 1; m &= m - 1;
                    int t3 = __ffs(m) - 1; m &= m - 1;
                    float w0 = __shfl_sync(FULL, wv, t0);
                    float w1 = __shfl_sync(FULL, wv, t1 & 31);
                    float w2 = __shfl_sync(FULL, wv, t2 & 31);
                    float w3 = __shfl_sync(FULL, wv, t3 & 31);
                    float4 g0 = d_xs_hs[(size_t)(base + t0) * 32 + lane];
                    float4 g1, g2, g3;
                    if (t1 >= 0) g1 = d_xs_hs[(size_t)(base + t1) * 32 + lane];
                    if (t2 >= 0) g2 = d_xs_hs[(size_t)(base + t2) * 32 + lane];
                    if (t3 >= 0) g3 = d_xs_hs[(size_t)(base + t3) * 32 + lane];
                    acc.x += w0*g0.x; acc.y += w0*g0.y; acc.z += w0*g0.z; acc.w += w0*g0.w;
                    if (t1 >= 0) { acc.x += w1*g1.x; acc.y += w1*g1.y; acc.z += w1*g1.z; acc.w += w1*g1.w; }
                    if (t2 >= 0) { acc.x += w2*g2.x; acc.y += w2*g2.y; acc.z += w2*g2.z; acc.w += w2*g2.w; }
                    if (t3 >= 0) { acc.x += w3*g3.x; acc.y += w3*g3.y; acc.z += w3*g3.z; acc.w += w3*g3.w; }
                }
            }
        }
    }
    d_xg_ms[(size_t)w * 32 + lane] = acc;
}

// ---------------- launch ----------------
extern "C" void kernel_launch(void* const* d_in, const int* in_sizes, int n_in,
                              void* d_out, int out_size) {
    const float* xs      = (const float*)d_in[0];
    const float* xg      = (const float*)d_in[1];
    const float* vs      = (const float*)d_in[2];
    const float* vg      = (const float*)d_in[3];
    const float* Ws_pre  = (const float*)d_in[4];
    const float* bs_pre  = (const float*)d_in[5];
    const float* Wg_pre  = (const float*)d_in[6];
    const float* bg_pre  = (const float*)d_in[7];
    const float* Ws_post = (const float*)d_in[8];
    const float* bs_post = (const float*)d_in[9];
    const float* Wg_post = (const float*)d_in[10];
    const float* bg_post = (const float*)d_in[11];
    float* out = (float*)d_out;
    (void)in_sizes; (void)n_in; (void)out_size;

    struct Res {
        cudaStream_t s1;
        cudaEvent_t  eBG, eBS, ePreS, eMPS, ePostS;
        Res() {
            cudaStreamCreateWithFlags(&s1, cudaStreamNonBlocking);
            cudaEventCreateWithFlags(&eBG,   cudaEventDisableTiming);
            cudaEventCreateWithFlags(&eBS,   cudaEventDisableTiming);
            cudaEventCreateWithFlags(&ePreS, cudaEventDisableTiming);
            cudaEventCreateWithFlags(&eMPS,  cudaEventDisableTiming);
            cudaEventCreateWithFlags(&ePostS,cudaEventDisableTiming);
        }
    };
    static Res R;

    // s0: binning chain
    k_zero<<<1, 512>>>();
    k_cellhist<true><<<TOT_S / 256, 256>>>(vs);
    k_cellhist<false><<<TOT_G / 256, 256>>>(vg);
    k_scan<<<1, 512>>>();
    k_build<false><<<NCELL, 128>>>(vg);
    cudaEventRecord(R.eBG, 0);
    k_build<true><<<NCELL, 128>>>(vs);
    cudaEventRecord(R.eBS, 0);

    // s1: pre_g -> mps
    cudaStreamWaitEvent(R.s1, R.eBG, 0);
    k_gemm_pre<false><<<TOT_G / GM, GT, 0, R.s1>>>(xg, Wg_pre, bg_pre);
    cudaStreamWaitEvent(R.s1, R.eBS, 0);
    k_mps<<<TOT_S / 16, 512, 0, R.s1>>>();
    cudaEventRecord(R.eMPS, R.s1);

    // s0: pre_s
    k_gemm_pre<true><<<TOT_S / GM, GT>>>(xs, Ws_pre, bs_pre);
    cudaEventRecord(R.ePreS, 0);

    // s0: mpg + post_g; s1: post_s
    cudaStreamWaitEvent(0, R.eMPS, 0);
    k_mpg<<<TOT_G / 16, 512>>>();
    k_gemm_post<false><<<TOT_G / GM, GT>>>(Wg_post, bg_post, out);

    cudaStreamWaitEvent(R.s1, R.ePreS, 0);
    k_gemm_post<true><<<TOT_S / GM, GT, 0, R.s1>>>(Ws_post, bs_post, out);
    cudaEventRecord(R.ePostS, R.s1);

    cudaStreamWaitEvent(0, R.ePostS, 0);
}